// round 2
// baseline (speedup 1.0000x reference)
#include <cuda_runtime.h>

// Fused LUT color-grade kernel for GB300 (sm_103a).
// x: (4, 3, 1024, 1024) f32, lut1d: (3, 64) f32, lut3d: (17,17,17,3) f32
// out = trilinear3d( clip01( lerp1d(x) ) ), same shape as x.

namespace {
constexpr int kHW      = 1024 * 1024;     // pixels per image plane
constexpr int kBatch   = 4;
constexpr int kN1      = 64;              // 1D LUT size
constexpr int kM       = 17;              // 3D LUT edge
constexpr int kM2      = kM * kM;         // 289
constexpr int kE3      = kM * kM * kM;    // 4913 entries
constexpr int kThreads = 512;
constexpr int kBlocks  = 304;             // 152 SMs * 2 resident CTAs
// smem: lut3d padded float4 (4913*16 B) + lut1d (192 floats)
constexpr int kSmemBytes = kE3 * 16 + 3 * kN1 * 4;  // 79376 B
}  // namespace

__device__ __forceinline__ float apply1d(const float* __restrict__ row, float v) {
    float xs = v * 63.0f;                       // (N1D - 1)
    int i = __float2int_rd(xs);
    i = max(0, min(i, 62));                     // clip(floor, 0, n-2)
    float f = xs - (float)i;
    float v0 = row[i];
    float v1 = row[i + 1];
    float y = fmaf(f, v1 - v0, v0);
    return fminf(fmaxf(y, 0.0f), 1.0f);         // clip to [0,1]
}

extern "C" __global__ void __launch_bounds__(kThreads, 2)
lut_fused_kernel(const float* __restrict__ x,
                 const float* __restrict__ lut1d,
                 const float* __restrict__ lut3d,
                 float* __restrict__ out)
{
    extern __shared__ float smem[];
    float4* __restrict__ s3 = reinterpret_cast<float4*>(smem);  // 4913 float4
    float*  __restrict__ s1 = smem + 4 * kE3;                   // 192 floats

    // Cooperative fill of shared LUTs (amortized over persistent grid).
    for (int i = threadIdx.x; i < kE3; i += kThreads) {
        s3[i] = make_float4(lut3d[3 * i + 0], lut3d[3 * i + 1],
                            lut3d[3 * i + 2], 0.0f);
    }
    for (int i = threadIdx.x; i < 3 * kN1; i += kThreads) {
        s1[i] = lut1d[i];
    }
    __syncthreads();

    const int ngroups = kBatch * (kHW / 4);   // 1,048,576 float4-groups
    const int stride  = gridDim.x * kThreads;

    for (int gid = blockIdx.x * kThreads + threadIdx.x; gid < ngroups;
         gid += stride) {
        int img = gid >> 18;                  // HW/4 = 2^18 groups per image
        int q   = (gid & 0x3FFFF) << 2;       // pixel offset within plane
        const float* bin  = x   + (size_t)img * 3 * kHW + q;
        float*       bout = out + (size_t)img * 3 * kHW + q;

        float4 vr = *reinterpret_cast<const float4*>(bin);
        float4 vg = *reinterpret_cast<const float4*>(bin + kHW);
        float4 vb = *reinterpret_cast<const float4*>(bin + 2 * kHW);

        float ri[4] = {vr.x, vr.y, vr.z, vr.w};
        float gi[4] = {vg.x, vg.y, vg.z, vg.w};
        float bi[4] = {vb.x, vb.y, vb.z, vb.w};
        float ro[4], go[4], bo[4];

#pragma unroll
        for (int k = 0; k < 4; ++k) {
            // ---- 1D LUT per channel + clip ----
            float yr = apply1d(s1,        ri[k]);
            float yg = apply1d(s1 + 64,   gi[k]);
            float yb = apply1d(s1 + 128,  bi[k]);

            // ---- 3D LUT trilinear ----
            float xr = yr * 16.0f;        // (M3D - 1)
            float xg = yg * 16.0f;
            float xb = yb * 16.0f;
            int ir = min(__float2int_rd(xr), 15);   // y >= 0 after clip
            int ig = min(__float2int_rd(xg), 15);
            int ib = min(__float2int_rd(xb), 15);
            float fr = xr - (float)ir;
            float fg = xg - (float)ig;
            float fb = xb - (float)ib;

            const float4* __restrict__ p = s3 + (ir * kM + ig) * kM + ib;

            float gb00 = (1.0f - fg) * (1.0f - fb);
            float gb01 = (1.0f - fg) * fb;
            float gb10 = fg * (1.0f - fb);
            float gb11 = fg * fb;

            // plane r = ir (bilinear over g,b)
            float4 c0 = p[0];
            float4 c1 = p[1];
            float s0x = c0.x * gb00 + c1.x * gb01;
            float s0y = c0.y * gb00 + c1.y * gb01;
            float s0z = c0.z * gb00 + c1.z * gb01;
            float4 c2 = p[kM];
            float4 c3 = p[kM + 1];
            s0x = fmaf(c2.x, gb10, s0x); s0x = fmaf(c3.x, gb11, s0x);
            s0y = fmaf(c2.y, gb10, s0y); s0y = fmaf(c3.y, gb11, s0y);
            s0z = fmaf(c2.z, gb10, s0z); s0z = fmaf(c3.z, gb11, s0z);

            // plane r = ir + 1
            const float4* __restrict__ p1 = p + kM2;
            float4 d0 = p1[0];
            float4 d1 = p1[1];
            float s1x = d0.x * gb00 + d1.x * gb01;
            float s1y = d0.y * gb00 + d1.y * gb01;
            float s1z = d0.z * gb00 + d1.z * gb01;
            float4 d2 = p1[kM];
            float4 d3 = p1[kM + 1];
            s1x = fmaf(d2.x, gb10, s1x); s1x = fmaf(d3.x, gb11, s1x);
            s1y = fmaf(d2.y, gb10, s1y); s1y = fmaf(d3.y, gb11, s1y);
            s1z = fmaf(d2.z, gb10, s1z); s1z = fmaf(d3.z, gb11, s1z);

            // lerp along r
            ro[k] = fmaf(fr, s1x - s0x, s0x);
            go[k] = fmaf(fr, s1y - s0y, s0y);
            bo[k] = fmaf(fr, s1z - s0z, s0z);
        }

        *reinterpret_cast<float4*>(bout)           = make_float4(ro[0], ro[1], ro[2], ro[3]);
        *reinterpret_cast<float4*>(bout + kHW)     = make_float4(go[0], go[1], go[2], go[3]);
        *reinterpret_cast<float4*>(bout + 2 * kHW) = make_float4(bo[0], bo[1], bo[2], bo[3]);
    }
}

extern "C" void kernel_launch(void* const* d_in, const int* in_sizes, int n_in,
                              void* d_out, int out_size) {
    (void)in_sizes; (void)n_in; (void)out_size;
    const float* x     = (const float*)d_in[0];
    const float* lut1d = (const float*)d_in[1];
    const float* lut3d = (const float*)d_in[2];
    float* out = (float*)d_out;

    // Opt into >48 KB dynamic smem (idempotent; not a stream op, capture-safe).
    (void)cudaFuncSetAttribute(lut_fused_kernel,
                               cudaFuncAttributeMaxDynamicSharedMemorySize,
                               kSmemBytes);

    lut_fused_kernel<<<kBlocks, kThreads, kSmemBytes>>>(x, lut1d, lut3d, out);
}

// round 4
// speedup vs baseline: 1.4778x; 1.4778x over previous
#include <cuda_runtime.h>
#include <cuda_fp16.h>

// Fused LUT color-grade, GB300 (sm_103a), round 3.
// x: (4,3,1024,1024) f32, lut1d: (3,64) f32, lut3d: (17,17,17,3) f32.
// Strategy: smem-bound workload -> minimize shared-memory bytes & wavefronts.
//  - 3D LUT repacked as per-(r-level, g, b) 2x2 corner tiles in fp16:
//      tile = 12 halfs = 24B, stored split as uint4 (16B) + uint2 (8B)
//      -> per pixel: 2 x (LDS.128 + LDS.64), zero wasted bytes.
//  - 1D LUT as float2 knot pairs -> 3 x LDS.64 per pixel.
//  - Tiled layout built once by a prep kernel into __device__ globals;
//    main kernel fills smem with coalesced uint4 copies.

namespace {
constexpr int kHW      = 1024 * 1024;
constexpr int kBatch   = 4;
constexpr int kM       = 17;            // 3D LUT edge
constexpr int kTiles   = 17 * 16 * 16;  // 4352 (r-level, g-cell, b-cell)
constexpr int kThreads = 512;
constexpr int kBlocks  = 304;           // 152 SMs * 2 CTAs
constexpr int kP1      = 3 * 63;        // 1D pair count

constexpr int kSA_u4 = kTiles;          // uint4 entries
constexpr int kSB_u2 = kTiles;          // uint2 entries
constexpr int kSmemBytes = kTiles * 16 + kTiles * 8 + 1536;  // 105,984 B
}  // namespace

__device__ uint4  g_tileA[kTiles];   // halfs: c00.r c00.g c00.b c01.r c01.g c01.b c10.r c10.g
__device__ uint2  g_tileB[kTiles];   // halfs: c10.b c11.r c11.g c11.b
__device__ float2 g_pair1d[kP1];     // (v[i], v[i+1]) per channel

static __device__ __forceinline__ unsigned pack2(float a, float b) {
    __half2 h = __halves2half2(__float2half(a), __float2half(b));
    return *reinterpret_cast<unsigned*>(&h);
}

extern "C" __global__ void lut_prep_kernel(const float* __restrict__ lut1d,
                                           const float* __restrict__ lut3d) {
    int t = blockIdx.x * blockDim.x + threadIdx.x;
    if (t < kTiles) {
        int l = t >> 8;            // r-level 0..16
        int g = (t >> 4) & 15;     // g-cell 0..15
        int b = t & 15;            // b-cell 0..15
        const float* base = lut3d + ((l * kM + g) * kM + b) * 3;
        // c00 = base[0..2], c01 = base[3..5] (b+1),
        // c10 = base[51..53] (g+1), c11 = base[54..56]
        float c[12];
#pragma unroll
        for (int j = 0; j < 6; ++j) c[j] = base[j];
#pragma unroll
        for (int j = 0; j < 6; ++j) c[6 + j] = base[51 + j];
        uint4 a;
        a.x = pack2(c[0], c[1]);   // c00.r c00.g
        a.y = pack2(c[2], c[3]);   // c00.b c01.r
        a.z = pack2(c[4], c[5]);   // c01.g c01.b
        a.w = pack2(c[6], c[7]);   // c10.r c10.g
        uint2 bb;
        bb.x = pack2(c[8], c[9]);  // c10.b c11.r
        bb.y = pack2(c[10], c[11]);// c11.g c11.b
        g_tileA[t] = a;
        g_tileB[t] = bb;
    }
    if (t < kP1) {
        int ch = t / 63, j = t - ch * 63;
        g_pair1d[t] = make_float2(lut1d[ch * 64 + j], lut1d[ch * 64 + j + 1]);
    }
}

__device__ __forceinline__ float apply1d_pair(const float2* __restrict__ s1,
                                              int ch, float v) {
    float xs = v * 63.0f;
    int i = __float2int_rd(xs);
    i = max(0, min(i, 62));
    float f = xs - (float)i;
    float2 p = s1[ch * 63 + i];            // LDS.64
    float y = fmaf(f, p.y - p.x, p.x);
    return fminf(fmaxf(y, 0.0f), 1.0f);
}

struct F3 { float x, y, z; };

__device__ __forceinline__ F3 bilerp_tile(uint4 a, uint2 b,
                                          float w00, float w01,
                                          float w10, float w11) {
    float2 p0 = __half22float2(*reinterpret_cast<__half2*>(&a.x));  // c00.r c00.g
    float2 p1 = __half22float2(*reinterpret_cast<__half2*>(&a.y));  // c00.b c01.r
    float2 p2 = __half22float2(*reinterpret_cast<__half2*>(&a.z));  // c01.g c01.b
    float2 p3 = __half22float2(*reinterpret_cast<__half2*>(&a.w));  // c10.r c10.g
    float2 p4 = __half22float2(*reinterpret_cast<__half2*>(&b.x));  // c10.b c11.r
    float2 p5 = __half22float2(*reinterpret_cast<__half2*>(&b.y));  // c11.g c11.b
    F3 s;
    s.x = fmaf(p4.y, w11, fmaf(p3.x, w10, fmaf(p1.y, w01, p0.x * w00)));
    s.y = fmaf(p5.x, w11, fmaf(p3.y, w10, fmaf(p2.x, w01, p0.y * w00)));
    s.z = fmaf(p5.y, w11, fmaf(p4.x, w10, fmaf(p2.y, w01, p1.x * w00)));
    return s;
}

extern "C" __global__ void __launch_bounds__(kThreads, 2)
lut_main_kernel(const float* __restrict__ x, float* __restrict__ out)
{
    extern __shared__ char smem[];
    uint4*  sA = reinterpret_cast<uint4*>(smem);
    uint2*  sB = reinterpret_cast<uint2*>(smem + kTiles * 16);
    float2* s1 = reinterpret_cast<float2*>(smem + kTiles * 16 + kTiles * 8);

    // Coalesced fill of staged tiled layout.
    for (int i = threadIdx.x; i < kSA_u4; i += kThreads) sA[i] = g_tileA[i];
    for (int i = threadIdx.x; i < kSB_u2; i += kThreads) sB[i] = g_tileB[i];
    for (int i = threadIdx.x; i < kP1;    i += kThreads) s1[i] = g_pair1d[i];
    __syncthreads();

    const int ngroups = kBatch * (kHW / 4);
    const int stride  = gridDim.x * kThreads;

    for (int gid = blockIdx.x * kThreads + threadIdx.x; gid < ngroups;
         gid += stride) {
        int img = gid >> 18;
        int q   = (gid & 0x3FFFF) << 2;
        const float* bin  = x   + (size_t)img * 3 * kHW + q;
        float*       bout = out + (size_t)img * 3 * kHW + q;

        float4 vr = *reinterpret_cast<const float4*>(bin);
        float4 vg = *reinterpret_cast<const float4*>(bin + kHW);
        float4 vb = *reinterpret_cast<const float4*>(bin + 2 * kHW);

        float ri[4] = {vr.x, vr.y, vr.z, vr.w};
        float gi[4] = {vg.x, vg.y, vg.z, vg.w};
        float bi[4] = {vb.x, vb.y, vb.z, vb.w};
        float ro[4], go[4], bo[4];

#pragma unroll
        for (int k = 0; k < 4; ++k) {
            // ---- 1D LUT + clip ----
            float yr = apply1d_pair(s1, 0, ri[k]);
            float yg = apply1d_pair(s1, 1, gi[k]);
            float yb = apply1d_pair(s1, 2, bi[k]);

            // ---- 3D trilinear via 2x2 tiles ----
            float xr = yr * 16.0f, xg = yg * 16.0f, xb = yb * 16.0f;
            int ir = min(__float2int_rd(xr), 15);
            int ig = min(__float2int_rd(xg), 15);
            int ib = min(__float2int_rd(xb), 15);
            float fr = xr - (float)ir;
            float fg = xg - (float)ig;
            float fb = xb - (float)ib;

            float wg0 = 1.0f - fg, wb0 = 1.0f - fb;
            float w00 = wg0 * wb0, w01 = wg0 * fb;
            float w10 = fg * wb0,  w11 = fg * fb;

            int t0 = (ir << 8) + (ig << 4) + ib;   // (ir*16+ig)*16+ib
            uint4 a0 = sA[t0];
            uint2 b0 = sB[t0];
            uint4 a1 = sA[t0 + 256];
            uint2 b1 = sB[t0 + 256];

            F3 sP = bilerp_tile(a0, b0, w00, w01, w10, w11);
            F3 sQ = bilerp_tile(a1, b1, w00, w01, w10, w11);

            ro[k] = fmaf(fr, sQ.x - sP.x, sP.x);
            go[k] = fmaf(fr, sQ.y - sP.y, sP.y);
            bo[k] = fmaf(fr, sQ.z - sP.z, sP.z);
        }

        *reinterpret_cast<float4*>(bout)           = make_float4(ro[0], ro[1], ro[2], ro[3]);
        *reinterpret_cast<float4*>(bout + kHW)     = make_float4(go[0], go[1], go[2], go[3]);
        *reinterpret_cast<float4*>(bout + 2 * kHW) = make_float4(bo[0], bo[1], bo[2], bo[3]);
    }
}

extern "C" void kernel_launch(void* const* d_in, const int* in_sizes, int n_in,
                              void* d_out, int out_size) {
    (void)in_sizes; (void)n_in; (void)out_size;
    const float* x     = (const float*)d_in[0];
    const float* lut1d = (const float*)d_in[1];
    const float* lut3d = (const float*)d_in[2];
    float* out = (float*)d_out;

    (void)cudaFuncSetAttribute(lut_main_kernel,
                               cudaFuncAttributeMaxDynamicSharedMemorySize,
                               kSmemBytes);

    // Stage tiled fp16 LUT layout (tiny; same stream -> ordered before main).
    lut_prep_kernel<<<(kTiles + 255) / 256, 256>>>(lut1d, lut3d);
    lut_main_kernel<<<kBlocks, kThreads, kSmemBytes>>>(x, out);
}

// round 5
// speedup vs baseline: 1.6514x; 1.1175x over previous
#include <cuda_runtime.h>
#include <cuda_fp16.h>

// Fused LUT color-grade, GB300 (sm_103a), round 5.
// x: (4,3,1024,1024) f32, lut1d: (3,64) f32, lut3d: (17,17,17,3) f32.
//
// Smem-wavefront-bound -> minimize LDS instructions & bytes per pixel:
//  - 3D LUT duplicated per CELL: 16^3 cells x 8 corners x 3ch fp16 = 48B/cell
//    = 196,608 B smem, fetched as exactly 3 x LDS.128 per pixel.
//  - 1D LUT knot pairs in fp16 half2 -> 3 x LDS.32 per pixel.
//  - 1 CTA/SM, 1024 threads (same 32 warps/SM residency as 2x512).

namespace {
constexpr int kHW      = 1024 * 1024;
constexpr int kBatch   = 4;
constexpr int kM       = 17;
constexpr int kCells   = 16 * 16 * 16;          // 4096
constexpr int kThreads = 1024;
// smem: cells SoA by 16B chunk: 3 planes of 4096 uint4 (196,608 B) + 1D (768 B)
constexpr int kSmemCells = kCells * 48;          // 196,608
constexpr int kSmemBytes = kSmemCells + 3 * 64 * 4;  // 197,376
}  // namespace

// Staged layouts (built once by prep kernel).
__device__ uint4    g_cells[3 * kCells];   // chunk-major: chunk j at [j*4096 + c]
__device__ __half2  g_pair1d[3 * 64];      // (v[i], v[i+1]) per channel, padded

static __device__ __forceinline__ unsigned pack2(float a, float b) {
    __half2 h = __halves2half2(__float2half(a), __float2half(b));
    return *reinterpret_cast<unsigned*>(&h);
}

extern "C" __global__ void lut_prep_kernel(const float* __restrict__ lut1d,
                                           const float* __restrict__ lut3d) {
    int t = blockIdx.x * blockDim.x + threadIdx.x;
    if (t < kCells) {
        int ir = t >> 8, ig = (t >> 4) & 15, ib = t & 15;
        float h[24];
#pragma unroll
        for (int corner = 0; corner < 8; ++corner) {
            int dr = corner >> 2, dg = (corner >> 1) & 1, db = corner & 1;
            const float* p =
                lut3d + (((ir + dr) * kM + (ig + dg)) * kM + (ib + db)) * 3;
            h[corner * 3 + 0] = p[0];
            h[corner * 3 + 1] = p[1];
            h[corner * 3 + 2] = p[2];
        }
#pragma unroll
        for (int j = 0; j < 3; ++j) {
            uint4 u;
            u.x = pack2(h[j * 8 + 0], h[j * 8 + 1]);
            u.y = pack2(h[j * 8 + 2], h[j * 8 + 3]);
            u.z = pack2(h[j * 8 + 4], h[j * 8 + 5]);
            u.w = pack2(h[j * 8 + 6], h[j * 8 + 7]);
            g_cells[j * kCells + t] = u;
        }
    }
    if (t < 3 * 64) {
        int ch = t >> 6, i = t & 63;
        float v0 = lut1d[ch * 64 + min(i, 62)];
        float v1 = lut1d[ch * 64 + min(i, 62) + 1];
        g_pair1d[t] = __halves2half2(__float2half(v0), __float2half(v1));
    }
}

__device__ __forceinline__ float apply1d_h2(const __half2* __restrict__ s1,
                                            int ch, float v) {
    float xs = v * 63.0f;
    int i = __float2int_rd(xs);
    i = max(0, min(i, 62));
    float f = xs - (float)i;
    float2 p = __half22float2(s1[ch * 64 + i]);   // LDS.32
    float y = fmaf(f, p.y - p.x, p.x);
    return fminf(fmaxf(y, 0.0f), 1.0f);
}

extern "C" __global__ void __launch_bounds__(kThreads, 1)
lut_main_kernel(const float* __restrict__ x, float* __restrict__ out,
                int ngrid)
{
    extern __shared__ char smem[];
    uint4*   sC = reinterpret_cast<uint4*>(smem);                    // 12288
    __half2* s1 = reinterpret_cast<__half2*>(smem + kSmemCells);     // 192

    for (int i = threadIdx.x; i < 3 * kCells; i += kThreads) sC[i] = g_cells[i];
    for (int i = threadIdx.x; i < 3 * 64;     i += kThreads) s1[i] = g_pair1d[i];
    __syncthreads();

    const int ngroups = kBatch * (kHW / 4);   // 1,048,576
    const int stride  = ngrid * kThreads;

    for (int gid = blockIdx.x * kThreads + threadIdx.x; gid < ngroups;
         gid += stride) {
        int img = gid >> 18;
        int q   = (gid & 0x3FFFF) << 2;
        const float* bin  = x   + (size_t)img * 3 * kHW + q;
        float*       bout = out + (size_t)img * 3 * kHW + q;

        float4 vr = *reinterpret_cast<const float4*>(bin);
        float4 vg = *reinterpret_cast<const float4*>(bin + kHW);
        float4 vb = *reinterpret_cast<const float4*>(bin + 2 * kHW);

        float ri[4] = {vr.x, vr.y, vr.z, vr.w};
        float gi[4] = {vg.x, vg.y, vg.z, vg.w};
        float bi[4] = {vb.x, vb.y, vb.z, vb.w};
        float ro[4], go[4], bo[4];

#pragma unroll
        for (int k = 0; k < 4; ++k) {
            // ---- 1D LUT + clip ----
            float yr = apply1d_h2(s1, 0, ri[k]);
            float yg = apply1d_h2(s1, 1, gi[k]);
            float yb = apply1d_h2(s1, 2, bi[k]);

            // ---- 3D trilinear from one 48B cell (3 x LDS.128) ----
            float xr = yr * 16.0f, xg = yg * 16.0f, xb = yb * 16.0f;
            int ir = min(__float2int_rd(xr), 15);
            int ig = min(__float2int_rd(xg), 15);
            int ib = min(__float2int_rd(xb), 15);
            float fr = xr - (float)ir;
            float fg = xg - (float)ig;
            float fb = xb - (float)ib;

            int c = (ir << 8) + (ig << 4) + ib;
            uint4 u0 = sC[c];
            uint4 u1 = sC[kCells + c];
            uint4 u2 = sC[2 * kCells + c];

            // unpack 24 halfs: corner ci = (dr*4+dg*2+db), h[ci*3 + ch]
            float2 p0 = __half22float2(*reinterpret_cast<__half2*>(&u0.x)); // h0 h1
            float2 p1 = __half22float2(*reinterpret_cast<__half2*>(&u0.y)); // h2 h3
            float2 p2 = __half22float2(*reinterpret_cast<__half2*>(&u0.z)); // h4 h5
            float2 p3 = __half22float2(*reinterpret_cast<__half2*>(&u0.w)); // h6 h7
            float2 p4 = __half22float2(*reinterpret_cast<__half2*>(&u1.x)); // h8 h9
            float2 p5 = __half22float2(*reinterpret_cast<__half2*>(&u1.y)); // h10 h11
            float2 p6 = __half22float2(*reinterpret_cast<__half2*>(&u1.z)); // h12 h13
            float2 p7 = __half22float2(*reinterpret_cast<__half2*>(&u1.w)); // h14 h15
            float2 p8 = __half22float2(*reinterpret_cast<__half2*>(&u2.x)); // h16 h17
            float2 p9 = __half22float2(*reinterpret_cast<__half2*>(&u2.y)); // h18 h19
            float2 pa = __half22float2(*reinterpret_cast<__half2*>(&u2.z)); // h20 h21
            float2 pb = __half22float2(*reinterpret_cast<__half2*>(&u2.w)); // h22 h23

            float wg0 = 1.0f - fg, wb0 = 1.0f - fb;
            float w00 = wg0 * wb0, w01 = wg0 * fb;
            float w10 = fg * wb0,  w11 = fg * fb;

            // plane r = ir : corners c000(h0..2) c001(h3..5) c010(h6..8) c011(h9..11)
            float s0r = fmaf(p3.x, w10, fmaf(p1.y, w01, p0.x * w00));
            s0r = fmaf(p4.y, w11, s0r);
            float s0g = fmaf(p3.y, w10, fmaf(p2.x, w01, p0.y * w00));
            s0g = fmaf(p5.x, w11, s0g);
            float s0b = fmaf(p4.x, w10, fmaf(p2.y, w01, p1.x * w00));
            s0b = fmaf(p5.y, w11, s0b);

            // plane r = ir+1 : c100(h12..14) c101(h15..17) c110(h18..20) c111(h21..23)
            float s1r = fmaf(p9.x, w10, fmaf(p7.y, w01, p6.x * w00));
            s1r = fmaf(pa.y, w11, s1r);
            float s1g = fmaf(p9.y, w10, fmaf(p8.x, w01, p6.y * w00));
            s1g = fmaf(pb.x, w11, s1g);
            float s1b = fmaf(pa.x, w10, fmaf(p8.y, w01, p7.x * w00));
            s1b = fmaf(pb.y, w11, s1b);

            ro[k] = fmaf(fr, s1r - s0r, s0r);
            go[k] = fmaf(fr, s1g - s0g, s0g);
            bo[k] = fmaf(fr, s1b - s0b, s0b);
        }

        *reinterpret_cast<float4*>(bout)           = make_float4(ro[0], ro[1], ro[2], ro[3]);
        *reinterpret_cast<float4*>(bout + kHW)     = make_float4(go[0], go[1], go[2], go[3]);
        *reinterpret_cast<float4*>(bout + 2 * kHW) = make_float4(bo[0], bo[1], bo[2], bo[3]);
    }
}

extern "C" void kernel_launch(void* const* d_in, const int* in_sizes, int n_in,
                              void* d_out, int out_size) {
    (void)in_sizes; (void)n_in; (void)out_size;
    const float* x     = (const float*)d_in[0];
    const float* lut1d = (const float*)d_in[1];
    const float* lut3d = (const float*)d_in[2];
    float* out = (float*)d_out;

    static int nsm = 0;
    if (nsm == 0) {
        cudaDeviceProp prop;
        cudaGetDeviceProperties(&prop, 0);
        nsm = prop.multiProcessorCount;          // 148 or 152
        cudaFuncSetAttribute(lut_main_kernel,
                             cudaFuncAttributeMaxDynamicSharedMemorySize,
                             kSmemBytes);
    }

    lut_prep_kernel<<<(kCells + 255) / 256, 256>>>(lut1d, lut3d);
    lut_main_kernel<<<nsm, kThreads, kSmemBytes>>>(x, out, nsm);
}

// round 6
// speedup vs baseline: 2.0222x; 1.2246x over previous
#include <cuda_runtime.h>
#include <cuda_fp16.h>

// Fused LUT color-grade, GB300 (sm_103a), round 6.
// x: (4,3,1024,1024) f32, lut1d: (3,64) f32, lut3d: (17,17,17,3) f32.
//
// L1-wavefront-bound -> compress per-cell payload 48B -> 32B:
//   chunk0: base c000 (3 fp16) + scale (fp16) + 7 int8 R-deltas + pad
//   chunk1: 7 int8 G-deltas + pad + 7 int8 B-deltas + pad
// res_ch = base_ch + (sum_c w_c * d_c) * scale/16384, computed with dp2a
// on s16-quantized weights (magic-number rounding, PRMT packing).

namespace {
constexpr int kHW      = 1024 * 1024;
constexpr int kBatch   = 4;
constexpr int kM       = 17;
constexpr int kCells   = 16 * 16 * 16;          // 4096
constexpr int kThreads = 1024;
constexpr int kSmemBytes = kCells * 32 + 3 * 64 * 4;  // 131,840 B
}  // namespace

__device__ uint4   g_c0[kCells];
__device__ uint4   g_c1[kCells];
__device__ __half2 g_pair1d[3 * 64];

static __device__ __forceinline__ unsigned packh2(float a, float b) {
    __half2 h = __halves2half2(__float2half(a), __float2half(b));
    return *reinterpret_cast<unsigned*>(&h);
}
static __device__ __forceinline__ unsigned pack4b(int b0, int b1, int b2, int b3) {
    return (unsigned)(b0 & 0xFF) | ((unsigned)(b1 & 0xFF) << 8) |
           ((unsigned)(b2 & 0xFF) << 16) | ((unsigned)(b3 & 0xFF) << 24);
}

extern "C" __global__ void lut_prep_kernel(const float* __restrict__ lut1d,
                                           const float* __restrict__ lut3d) {
    int t = blockIdx.x * blockDim.x + threadIdx.x;
    if (t < kCells) {
        int ir = t >> 8, ig = (t >> 4) & 15, ib = t & 15;
        float v[8][3];
#pragma unroll
        for (int c = 0; c < 8; ++c) {
            int dr = c >> 2, dg = (c >> 1) & 1, db = c & 1;
            const float* p =
                lut3d + (((ir + dr) * kM + (ig + dg)) * kM + (ib + db)) * 3;
            v[c][0] = p[0]; v[c][1] = p[1]; v[c][2] = p[2];
        }
        float d[8][3];
        float maxd = 0.0f;
#pragma unroll
        for (int c = 1; c < 8; ++c)
#pragma unroll
            for (int ch = 0; ch < 3; ++ch) {
                d[c][ch] = v[c][ch] - v[0][ch];
                maxd = fmaxf(maxd, fabsf(d[c][ch]));
            }
        float inv = (maxd > 0.0f) ? 127.0f / maxd : 0.0f;
        int q[8][3];
#pragma unroll
        for (int c = 1; c < 8; ++c)
#pragma unroll
            for (int ch = 0; ch < 3; ++ch) {
                int qq = __float2int_rn(d[c][ch] * inv);
                q[c][ch] = max(-127, min(127, qq));
            }
        float scale = maxd * (1.0f / 127.0f);

        uint4 c0, c1;
        c0.x = packh2(v[0][0], v[0][1]);                  // base r,g
        c0.y = packh2(v[0][2], scale);                    // base b, scale
        c0.z = pack4b(q[1][0], q[2][0], q[3][0], q[4][0]);// dR c1..c4
        c0.w = pack4b(q[5][0], q[6][0], q[7][0], 0);      // dR c5..c7,0
        c1.x = pack4b(q[1][1], q[2][1], q[3][1], q[4][1]);// dG
        c1.y = pack4b(q[5][1], q[6][1], q[7][1], 0);
        c1.z = pack4b(q[1][2], q[2][2], q[3][2], q[4][2]);// dB
        c1.w = pack4b(q[5][2], q[6][2], q[7][2], 0);
        g_c0[t] = c0;
        g_c1[t] = c1;
    }
    if (t < 3 * 64) {
        int ch = t >> 6, i = t & 63;
        float v0 = lut1d[ch * 64 + min(i, 62)];
        float v1 = lut1d[ch * 64 + min(i, 62) + 1];
        g_pair1d[t] = __halves2half2(__float2half(v0), __float2half(v1));
    }
}

__device__ __forceinline__ float apply1d_h2(const __half2* __restrict__ s1,
                                            int ch, float v) {
    float xs = v * 63.0f;
    int i = __float2int_rd(xs);
    i = max(0, min(i, 62));
    float f = xs - (float)i;
    float2 p = __half22float2(s1[ch * 64 + i]);
    float y = fmaf(f, p.y - p.x, p.x);
    return fminf(fmaxf(y, 0.0f), 1.0f);
}

__device__ __forceinline__ int dp2a_lo(unsigned a, unsigned b, int c) {
    int d;
    asm("dp2a.lo.s32.s32 %0, %1, %2, %3;" : "=r"(d) : "r"(a), "r"(b), "r"(c));
    return d;
}
__device__ __forceinline__ int dp2a_hi(unsigned a, unsigned b, int c) {
    int d;
    asm("dp2a.hi.s32.s32 %0, %1, %2, %3;" : "=r"(d) : "r"(a), "r"(b), "r"(c));
    return d;
}
// low 16 bits of a and b combined: (a&0xFFFF) | (b<<16)
__device__ __forceinline__ unsigned prmt_lo16(unsigned a, unsigned b) {
    unsigned d;
    asm("prmt.b32 %0, %1, %2, 0x5410;" : "=r"(d) : "r"(a), "r"(b));
    return d;
}

extern "C" __global__ void __launch_bounds__(kThreads, 1)
lut_main_kernel(const float* __restrict__ x, float* __restrict__ out,
                int ngrid)
{
    extern __shared__ char smem[];
    uint4*   sC0 = reinterpret_cast<uint4*>(smem);                     // 4096
    uint4*   sC1 = reinterpret_cast<uint4*>(smem + kCells * 16);       // 4096
    __half2* s1  = reinterpret_cast<__half2*>(smem + kCells * 32);     // 192

    for (int i = threadIdx.x; i < kCells; i += kThreads) sC0[i] = g_c0[i];
    for (int i = threadIdx.x; i < kCells; i += kThreads) sC1[i] = g_c1[i];
    for (int i = threadIdx.x; i < 3 * 64; i += kThreads) s1[i]  = g_pair1d[i];
    __syncthreads();

    const float kMagic = 12582912.0f;   // 1.5 * 2^23 : round-to-int in mantissa
    const int ngroups = kBatch * (kHW / 4);
    const int stride  = ngrid * kThreads;

    for (int gid = blockIdx.x * kThreads + threadIdx.x; gid < ngroups;
         gid += stride) {
        int img = gid >> 18;
        int q   = (gid & 0x3FFFF) << 2;
        const float* bin  = x   + (size_t)img * 3 * kHW + q;
        float*       bout = out + (size_t)img * 3 * kHW + q;

        float4 vr = *reinterpret_cast<const float4*>(bin);
        float4 vg = *reinterpret_cast<const float4*>(bin + kHW);
        float4 vb = *reinterpret_cast<const float4*>(bin + 2 * kHW);

        float ri[4] = {vr.x, vr.y, vr.z, vr.w};
        float gi[4] = {vg.x, vg.y, vg.z, vg.w};
        float bi[4] = {vb.x, vb.y, vb.z, vb.w};
        float ro[4], go[4], bo[4];

#pragma unroll
        for (int k = 0; k < 4; ++k) {
            // ---- 1D LUT + clip ----
            float yr = apply1d_h2(s1, 0, ri[k]);
            float yg = apply1d_h2(s1, 1, gi[k]);
            float yb = apply1d_h2(s1, 2, bi[k]);

            // ---- indices & fractions ----
            float xr = yr * 16.0f, xg = yg * 16.0f, xb = yb * 16.0f;
            int ir = min(__float2int_rd(xr), 15);
            int ig = min(__float2int_rd(xg), 15);
            int ib = min(__float2int_rd(xb), 15);
            float fr = xr - (float)ir;
            float fg = xg - (float)ig;
            float fb = xb - (float)ib;

            // ---- weights (x16384), s16-quantized via magic rounding ----
            float a0 = 1.0f - fr, g0 = 1.0f - fg;
            float b0s = (1.0f - fb) * 16384.0f, b1s = fb * 16384.0f;
            float t00 = g0 * b0s, t01 = g0 * b1s;
            float t10 = fg * b0s, t11 = fg * b1s;
            // corners c1..c7 = (0,0,1)(0,1,0)(0,1,1)(1,0,0)(1,0,1)(1,1,0)(1,1,1)
            unsigned m1 = __float_as_uint(fmaf(a0, t01, kMagic));
            unsigned m2 = __float_as_uint(fmaf(a0, t10, kMagic));
            unsigned m3 = __float_as_uint(fmaf(a0, t11, kMagic));
            unsigned m4 = __float_as_uint(fmaf(fr, t00, kMagic));
            unsigned m5 = __float_as_uint(fmaf(fr, t01, kMagic));
            unsigned m6 = __float_as_uint(fmaf(fr, t10, kMagic));
            unsigned m7 = __float_as_uint(fmaf(fr, t11, kMagic));
            unsigned wp0 = prmt_lo16(m1, m2);   // (W1, W2) for bytes 0,1
            unsigned wp1 = prmt_lo16(m3, m4);   // (W3, W4) for bytes 2,3
            unsigned wp2 = prmt_lo16(m5, m6);   // (W5, W6)
            unsigned wp3 = m7 & 0xFFFF;         // (W7, 0)

            // ---- one 32B cell: 2 x LDS.128 ----
            int c = (ir << 8) + (ig << 4) + ib;
            uint4 u0 = sC0[c];
            uint4 u1 = sC1[c];

            int aR = dp2a_lo(wp0, u0.z, 0);
            aR = dp2a_hi(wp1, u0.z, aR);
            aR = dp2a_lo(wp2, u0.w, aR);
            aR = dp2a_hi(wp3, u0.w, aR);
            int aG = dp2a_lo(wp0, u1.x, 0);
            aG = dp2a_hi(wp1, u1.x, aG);
            aG = dp2a_lo(wp2, u1.y, aG);
            aG = dp2a_hi(wp3, u1.y, aG);
            int aB = dp2a_lo(wp0, u1.z, 0);
            aB = dp2a_hi(wp1, u1.z, aB);
            aB = dp2a_lo(wp2, u1.w, aB);
            aB = dp2a_hi(wp3, u1.w, aB);

            float2 brg = __half22float2(*reinterpret_cast<__half2*>(&u0.x));
            float2 bbs = __half22float2(*reinterpret_cast<__half2*>(&u0.y));
            float fs = bbs.y * (1.0f / 16384.0f);

            ro[k] = fmaf((float)aR, fs, brg.x);
            go[k] = fmaf((float)aG, fs, brg.y);
            bo[k] = fmaf((float)aB, fs, bbs.x);
        }

        *reinterpret_cast<float4*>(bout)           = make_float4(ro[0], ro[1], ro[2], ro[3]);
        *reinterpret_cast<float4*>(bout + kHW)     = make_float4(go[0], go[1], go[2], go[3]);
        *reinterpret_cast<float4*>(bout + 2 * kHW) = make_float4(bo[0], bo[1], bo[2], bo[3]);
    }
}

extern "C" void kernel_launch(void* const* d_in, const int* in_sizes, int n_in,
                              void* d_out, int out_size) {
    (void)in_sizes; (void)n_in; (void)out_size;
    const float* x     = (const float*)d_in[0];
    const float* lut1d = (const float*)d_in[1];
    const float* lut3d = (const float*)d_in[2];
    float* out = (float*)d_out;

    static int nsm = 0;
    if (nsm == 0) {
        cudaDeviceProp prop;
        cudaGetDeviceProperties(&prop, 0);
        nsm = prop.multiProcessorCount;
        cudaFuncSetAttribute(lut_main_kernel,
                             cudaFuncAttributeMaxDynamicSharedMemorySize,
                             kSmemBytes);
    }

    lut_prep_kernel<<<(kCells + 255) / 256, 256>>>(lut1d, lut3d);
    lut_main_kernel<<<nsm, kThreads, kSmemBytes>>>(x, out, nsm);
}